// round 15
// baseline (speedup 1.0000x reference)
#include <cuda_runtime.h>

#define NS 8192
#define NH 64
#define CC 64
#define TILES 4

// Scratch (allocation-free rule: __device__ globals)
__device__ float g_X1[NS * CC];
__device__ float g_X2[NS * CC];

// ---------------------------------------------------------------------------
// Kernel 1 (exact R8/R12 version — best known at 38.2 us): 4 tiles per CTA,
// 256 threads, all 16 float4 loads front-batched, register-resident reductions.
// ---------------------------------------------------------------------------
__global__ void __launch_bounds__(256) prep_kernel(
    const float* __restrict__ Hp, const float* __restrict__ w1,
    const float* __restrict__ W2, const float* __restrict__ w3)
{
    __shared__ float t_sm[TILES][64];
    const int s0   = blockIdx.x * TILES;
    const int tid  = threadIdx.x;
    const int lane = tid & 31;

    ((float*)t_sm)[tid] = 0.f;   // 256 floats == TILES*64

    // Front-batched streaming loads (read-once: evict-first)
    const float4* base = (const float4*)(Hp + (size_t)s0 * (CC * NH));
    float4 v[TILES][4];
    #pragma unroll
    for (int p = 0; p < TILES; p++)
        #pragma unroll
        for (int k = 0; k < 4; k++)
            v[p][k] = __ldcs(base + p * 1024 + tid + 256 * k);

    const int h0 = (tid & 15) * 4;
    const int c0 = tid >> 4;
    const float w3v0 = __ldg(w3 + h0),     w3v1 = __ldg(w3 + h0 + 1);
    const float w3v2 = __ldg(w3 + h0 + 2), w3v3 = __ldg(w3 + h0 + 3);
    float w1c[4];
    #pragma unroll
    for (int k = 0; k < 4; k++) w1c[k] = __ldg(w1 + c0 + 16 * k);

    __syncthreads();   // t_sm init visible before atomics

    #pragma unroll
    for (int p = 0; p < TILES; p++) {
        float tq0 = 0.f, tq1 = 0.f, tq2 = 0.f, tq3 = 0.f;
        #pragma unroll
        for (int k = 0; k < 4; k++) {
            tq0 += v[p][k].x * w1c[k];  tq1 += v[p][k].y * w1c[k];
            tq2 += v[p][k].z * w1c[k];  tq3 += v[p][k].w * w1c[k];

            float d = v[p][k].x * w3v0 + v[p][k].y * w3v1
                    + v[p][k].z * w3v2 + v[p][k].w * w3v3;
            #pragma unroll
            for (int o = 8; o; o >>= 1) d += __shfl_xor_sync(0xffffffffu, d, o);
            if ((lane & 15) == 0)
                g_X2[(size_t)(s0 + p) * CC + c0 + 16 * k] = d;
        }
        tq0 += __shfl_xor_sync(0xffffffffu, tq0, 16);
        tq1 += __shfl_xor_sync(0xffffffffu, tq1, 16);
        tq2 += __shfl_xor_sync(0xffffffffu, tq2, 16);
        tq3 += __shfl_xor_sync(0xffffffffu, tq3, 16);
        if (lane < 16) {
            atomicAdd(&t_sm[p][h0],     tq0);
            atomicAdd(&t_sm[p][h0 + 1], tq1);
            atomicAdd(&t_sm[p][h0 + 2], tq2);
            atomicAdd(&t_sm[p][h0 + 3], tq3);
        }
    }
    __syncthreads();

    const int cp   = tid >> 2;
    const int part = tid & 3;
    const float4* w2v = (const float4*)(W2 + cp * NH + part * 16);
    float4 w[4];
    #pragma unroll
    for (int j = 0; j < 4; j++) w[j] = __ldg(&w2v[j]);

    #pragma unroll
    for (int p = 0; p < TILES; p++) {
        const float* tp = &t_sm[p][part * 16];
        float acc = 0.f;
        #pragma unroll
        for (int j = 0; j < 4; j++)
            acc += w[j].x * tp[4*j] + w[j].y * tp[4*j+1]
                 + w[j].z * tp[4*j+2] + w[j].w * tp[4*j+3];
        acc += __shfl_xor_sync(0xffffffffu, acc, 1);
        acc += __shfl_xor_sync(0xffffffffu, acc, 2);
        if (part == 0) g_X1[(size_t)(s0 + p) * CC + cp] = acc;
    }
}

// ---------------------------------------------------------------------------
// Kernel 2: R12 row_kernel + fused V/B gather in compaction. The discovering
// thread issues the two scattered DRAM loads for its hit immediately, so all
// ~82 gathered sectors per row fly in ONE parallel burst during phase A.
// Phase B then touches only L2-resident X2 + smem. Zero-writes stay here
// (measured nearly free: 11.9 TB/s marginal in R12 vs 6.9 TB/s in prep).
// ---------------------------------------------------------------------------
#define MAXM 2048   // binomial(8192, 0.01): mean 82, std 9 — huge margin

__global__ void __launch_bounds__(512) row_kernel(
    const float* __restrict__ V, const float* __restrict__ B,
    const unsigned int* __restrict__ mask, float* __restrict__ out)
{
    __shared__ int   idxs[MAXM];    // 8 KB compacted column indices
    __shared__ float v_sm[MAXM];    // 8 KB gathered V values
    __shared__ float b_sm[MAXM];    // 8 KB gathered B values
    __shared__ float e_c[MAXM];     // 8 KB compacted e values
    __shared__ float x1s[64];
    __shared__ float rowsum;
    __shared__ int   cnt;

    const int s    = blockIdx.x;
    const int tid  = threadIdx.x;
    const int lane = tid & 31;
    const int wid  = tid >> 5;
    const size_t rowoff = (size_t)s * NS;

    if (tid == 0) { cnt = 0; rowsum = 1e-6f; }
    if (tid < 64) x1s[tid] = g_X1[(size_t)s * CC + tid];

    // Front-batch the mask loads (evict-first: read exactly once)
    const uint4* mv = (const uint4*)(mask + rowoff);
    uint4 u[4];
    #pragma unroll
    for (int k = 0; k < 4; k++) u[k] = __ldcs(mv + tid + k * 512);

    // Fire-and-forget streaming zero write of the output row
    float4* out4 = (float4*)(out + rowoff);
    const float4 z4 = make_float4(0.f, 0.f, 0.f, 0.f);
    #pragma unroll
    for (int k = 0; k < 4; k++) __stcs(out4 + tid + k * 512, z4);

    __syncthreads();   // cnt/rowsum/x1s visible

    // --- Phase A: warp-aggregated compaction + fused V/B gather -------------
    int nh = 0;
    #pragma unroll
    for (int k = 0; k < 4; k++)
        nh += (u[k].x ? 1 : 0) + (u[k].y ? 1 : 0)
            + (u[k].z ? 1 : 0) + (u[k].w ? 1 : 0);

    int incl = nh;
    #pragma unroll
    for (int o = 1; o < 32; o <<= 1) {
        int t = __shfl_up_sync(0xffffffffu, incl, o);
        if (lane >= o) incl += t;
    }
    int wbase = 0;
    if (lane == 31 && incl > 0) wbase = atomicAdd(&cnt, incl);
    wbase = __shfl_sync(0xffffffffu, wbase, 31);

    int pos = wbase + incl - nh;   // exclusive prefix within warp
    #pragma unroll
    for (int k = 0; k < 4; k++) {
        if (u[k].x | u[k].y | u[k].z | u[k].w) {
            const int bj = (tid + k * 512) * 4;
            #pragma unroll
            for (int q = 0; q < 4; q++) {
                const unsigned int bit = (q == 0) ? u[k].x : (q == 1) ? u[k].y
                                       : (q == 2) ? u[k].z : u[k].w;
                if (bit) {
                    const int j = bj + q;
                    idxs[pos] = j;
                    v_sm[pos] = __ldg(V + rowoff + j);   // scattered DRAM,
                    b_sm[pos] = __ldg(B + rowoff + j);   // all in flight now
                    pos++;
                }
            }
        }
    }
    __syncthreads();
    const int m = cnt;

    // --- Phase B: half-warp per element (X2 from L2, V/B from smem) ---------
    const int half = lane >> 4;                       // 0 or 1
    const int hl   = lane & 15;
    const unsigned hmask = 0xFFFFu << (half * 16);
    const float4 x1v = *(const float4*)(x1s + hl * 4);
    float lsum = 0.f;

    for (int el = wid * 2 + half; el < m; el += 32) {
        const int j = idxs[el];
        const float4 xv = __ldg((const float4*)(g_X2 + (size_t)j * CC) + hl);
        float p = xv.x * x1v.x + xv.y * x1v.y + xv.z * x1v.z + xv.w * x1v.w;
        #pragma unroll
        for (int o = 8; o; o >>= 1) p += __shfl_xor_sync(hmask, p, o);
        if (hl == 0) {
            const float sg = 1.f / (1.f + expf(-(p + b_sm[el])));
            const float ev = expf(v_sm[el] * sg);
            e_c[el] = ev;
            lsum += ev;
        }
    }

    // --- Row sum: warp reduce + one smem atomic per warp --------------------
    #pragma unroll
    for (int o = 16; o; o >>= 1) lsum += __shfl_down_sync(0xffffffffu, lsum, o);
    if (lane == 0 && lsum != 0.f) atomicAdd(&rowsum, lsum);
    __syncthreads();

    // --- Sparse scatter of scaled values over the zeros ---------------------
    const float inv = 1.f / rowsum;
    for (int el = tid; el < m; el += 512)
        __stcs(out + rowoff + idxs[el], e_c[el] * inv);
}

extern "C" void kernel_launch(void* const* d_in, const int* in_sizes, int n_in,
                              void* d_out, int out_size)
{
    (void)in_sizes; (void)n_in; (void)out_size;
    const float* Hp  = (const float*)d_in[0];
    const float* w1  = (const float*)d_in[1];
    const float* W2  = (const float*)d_in[2];
    const float* w3  = (const float*)d_in[3];
    const float* V   = (const float*)d_in[4];
    const float* B   = (const float*)d_in[5];
    const unsigned int* mask = (const unsigned int*)d_in[6];
    float* out = (float*)d_out;

    prep_kernel<<<NS / TILES, 256>>>(Hp, w1, W2, w3);
    row_kernel<<<NS, 512>>>(V, B, mask, out);
}

// round 16
// speedup vs baseline: 1.2267x; 1.2267x over previous
#include <cuda_runtime.h>

#define NS 8192
#define NH 64
#define CC 64
#define TILES 4

// Scratch (allocation-free rule: __device__ globals)
__device__ float g_X1[NS * CC];
__device__ float g_X2[NS * CC];

// ---------------------------------------------------------------------------
// Kernel 1: 4 tiles per CTA, 256 threads, DOUBLE-BUFFERED: tile p+1's four
// LDG.128 fly while tile p is reduced. 16 data regs live per stage (vs 64
// front-batched) -> ~56 regs, 4 CTAs/SM instead of 3, sustained MLP.
// ---------------------------------------------------------------------------
__global__ void __launch_bounds__(256) prep_kernel(
    const float* __restrict__ Hp, const float* __restrict__ w1,
    const float* __restrict__ W2, const float* __restrict__ w3)
{
    __shared__ float t_sm[TILES][64];
    const int tid  = threadIdx.x;
    const int lane = tid & 31;

    ((float*)t_sm)[tid] = 0.f;   // 256 floats == TILES*64

    const float4* base = (const float4*)(Hp + (size_t)(blockIdx.x * TILES) * (CC * NH));
    float4 v[2][4];
    #pragma unroll
    for (int k = 0; k < 4; k++) v[0][k] = __ldcs(base + tid + 256 * k);

    const int h0 = (tid & 15) * 4;
    const int c0 = tid >> 4;
    const float w3v0 = __ldg(w3 + h0),     w3v1 = __ldg(w3 + h0 + 1);
    const float w3v2 = __ldg(w3 + h0 + 2), w3v3 = __ldg(w3 + h0 + 3);
    float w1c[4];
    #pragma unroll
    for (int k = 0; k < 4; k++) w1c[k] = __ldg(w1 + c0 + 16 * k);

    __syncthreads();   // t_sm init visible before atomics

    #pragma unroll
    for (int p = 0; p < TILES; p++) {
        const int cur = p & 1;
        // Prefetch next tile while this one is reduced
        if (p + 1 < TILES) {
            #pragma unroll
            for (int k = 0; k < 4; k++)
                v[cur ^ 1][k] = __ldcs(base + (p + 1) * 1024 + tid + 256 * k);
        }

        float tq0 = 0.f, tq1 = 0.f, tq2 = 0.f, tq3 = 0.f;
        #pragma unroll
        for (int k = 0; k < 4; k++) {
            tq0 += v[cur][k].x * w1c[k];  tq1 += v[cur][k].y * w1c[k];
            tq2 += v[cur][k].z * w1c[k];  tq3 += v[cur][k].w * w1c[k];

            float d = v[cur][k].x * w3v0 + v[cur][k].y * w3v1
                    + v[cur][k].z * w3v2 + v[cur][k].w * w3v3;
            #pragma unroll
            for (int o = 8; o; o >>= 1) d += __shfl_xor_sync(0xffffffffu, d, o);
            if ((lane & 15) == 0)
                g_X2[(size_t)(blockIdx.x * TILES + p) * CC + c0 + 16 * k] = d;
        }
        tq0 += __shfl_xor_sync(0xffffffffu, tq0, 16);
        tq1 += __shfl_xor_sync(0xffffffffu, tq1, 16);
        tq2 += __shfl_xor_sync(0xffffffffu, tq2, 16);
        tq3 += __shfl_xor_sync(0xffffffffu, tq3, 16);
        if (lane < 16) {
            atomicAdd(&t_sm[p][h0],     tq0);
            atomicAdd(&t_sm[p][h0 + 1], tq1);
            atomicAdd(&t_sm[p][h0 + 2], tq2);
            atomicAdd(&t_sm[p][h0 + 3], tq3);
        }
    }
    __syncthreads();

    const int cp   = tid >> 2;
    const int part = tid & 3;
    const float4* w2v = (const float4*)(W2 + cp * NH + part * 16);
    float4 w[4];
    #pragma unroll
    for (int j = 0; j < 4; j++) w[j] = __ldg(&w2v[j]);

    #pragma unroll
    for (int p = 0; p < TILES; p++) {
        const float* tp = &t_sm[p][part * 16];
        float acc = 0.f;
        #pragma unroll
        for (int j = 0; j < 4; j++)
            acc += w[j].x * tp[4*j] + w[j].y * tp[4*j+1]
                 + w[j].z * tp[4*j+2] + w[j].w * tp[4*j+3];
        acc += __shfl_xor_sync(0xffffffffu, acc, 1);
        acc += __shfl_xor_sync(0xffffffffu, acc, 2);
        if (part == 0)
            g_X1[(size_t)(blockIdx.x * TILES + p) * CC + cp] = acc;
    }
}

// ---------------------------------------------------------------------------
// Kernel 2: exact R12 row_kernel (best known: 126.2 us, regs 32, occ 95%)
// + __ldcs on phase-B V/B loads (touched once; preserves L2 for X2).
// ---------------------------------------------------------------------------
#define MAXM 2048   // binomial(8192, 0.01): mean 82, std 9 — huge margin

__global__ void __launch_bounds__(512) row_kernel(
    const float* __restrict__ V, const float* __restrict__ B,
    const unsigned int* __restrict__ mask, float* __restrict__ out)
{
    __shared__ int   idxs[MAXM];    // 8 KB compacted column indices
    __shared__ float e_c[MAXM];     // 8 KB compacted e values
    __shared__ float x1s[64];
    __shared__ float rowsum;
    __shared__ int   cnt;

    const int s    = blockIdx.x;
    const int tid  = threadIdx.x;
    const int lane = tid & 31;
    const int wid  = tid >> 5;
    const size_t rowoff = (size_t)s * NS;

    if (tid == 0) { cnt = 0; rowsum = 1e-6f; }
    if (tid < 64) x1s[tid] = g_X1[(size_t)s * CC + tid];

    // Front-batch the mask loads (evict-first: read exactly once)
    const uint4* mv = (const uint4*)(mask + rowoff);
    uint4 u[4];
    #pragma unroll
    for (int k = 0; k < 4; k++) u[k] = __ldcs(mv + tid + k * 512);

    // Fire-and-forget streaming zero write of the output row
    float4* out4 = (float4*)(out + rowoff);
    const float4 z4 = make_float4(0.f, 0.f, 0.f, 0.f);
    #pragma unroll
    for (int k = 0; k < 4; k++) __stcs(out4 + tid + k * 512, z4);

    __syncthreads();   // cnt/rowsum/x1s visible

    // --- Phase A: warp-aggregated compaction --------------------------------
    int nh = 0;
    #pragma unroll
    for (int k = 0; k < 4; k++)
        nh += (u[k].x ? 1 : 0) + (u[k].y ? 1 : 0)
            + (u[k].z ? 1 : 0) + (u[k].w ? 1 : 0);

    int incl = nh;
    #pragma unroll
    for (int o = 1; o < 32; o <<= 1) {
        int t = __shfl_up_sync(0xffffffffu, incl, o);
        if (lane >= o) incl += t;
    }
    int wbase = 0;
    if (lane == 31 && incl > 0) wbase = atomicAdd(&cnt, incl);
    wbase = __shfl_sync(0xffffffffu, wbase, 31);

    int pos = wbase + incl - nh;   // exclusive prefix within warp
    #pragma unroll
    for (int k = 0; k < 4; k++) {
        if (u[k].x | u[k].y | u[k].z | u[k].w) {
            const int bj = (tid + k * 512) * 4;
            if (u[k].x) idxs[pos++] = bj;
            if (u[k].y) idxs[pos++] = bj + 1;
            if (u[k].z) idxs[pos++] = bj + 2;
            if (u[k].w) idxs[pos++] = bj + 3;
        }
    }
    __syncthreads();
    const int m = cnt;

    // --- Phase B: half-warp per element ------------------------------------
    const int half = lane >> 4;                       // 0 or 1
    const int hl   = lane & 15;
    const unsigned hmask = 0xFFFFu << (half * 16);
    const float4 x1v = *(const float4*)(x1s + hl * 4);
    float lsum = 0.f;

    for (int el = wid * 2 + half; el < m; el += 32) {
        const int j = idxs[el];
        const float bb = __ldcs(B + rowoff + j);      // once-only: evict-first
        const float vv = __ldcs(V + rowoff + j);
        const float4 xv = __ldg((const float4*)(g_X2 + (size_t)j * CC) + hl);
        float p = xv.x * x1v.x + xv.y * x1v.y + xv.z * x1v.z + xv.w * x1v.w;
        #pragma unroll
        for (int o = 8; o; o >>= 1) p += __shfl_xor_sync(hmask, p, o);
        if (hl == 0) {
            const float sg = 1.f / (1.f + expf(-(p + bb)));
            const float ev = expf(vv * sg);
            e_c[el] = ev;
            lsum += ev;
        }
    }

    // --- Row sum: warp reduce + one smem atomic per warp --------------------
    #pragma unroll
    for (int o = 16; o; o >>= 1) lsum += __shfl_down_sync(0xffffffffu, lsum, o);
    if (lane == 0 && lsum != 0.f) atomicAdd(&rowsum, lsum);
    __syncthreads();

    // --- Sparse scatter of scaled values over the zeros ---------------------
    const float inv = 1.f / rowsum;
    for (int el = tid; el < m; el += 512)
        __stcs(out + rowoff + idxs[el], e_c[el] * inv);
}

extern "C" void kernel_launch(void* const* d_in, const int* in_sizes, int n_in,
                              void* d_out, int out_size)
{
    (void)in_sizes; (void)n_in; (void)out_size;
    const float* Hp  = (const float*)d_in[0];
    const float* w1  = (const float*)d_in[1];
    const float* W2  = (const float*)d_in[2];
    const float* w3  = (const float*)d_in[3];
    const float* V   = (const float*)d_in[4];
    const float* B   = (const float*)d_in[5];
    const unsigned int* mask = (const unsigned int*)d_in[6];
    float* out = (float*)d_out;

    prep_kernel<<<NS / TILES, 256>>>(Hp, w1, W2, w3);
    row_kernel<<<NS, 512>>>(V, B, mask, out);
}